// round 12
// baseline (speedup 1.0000x reference)
#include <cuda_runtime.h>

#define B_SZ 1024
#define N_SZ 16
#define T_SZ 256
#define SC   5     // columns 0..4 of L live in thread-private smem
#define SM_ELEMS 70  // 16+15+14+13+12 elements in smem per thread
#define AR_ELEMS 66  // remaining triangle (cols 5..15) in registers

// slot for smem-resident columns j < SC (compile-time folded after unroll)
__device__ __forceinline__ int slot_s(int i, int j) {
    return j * N_SZ - (j * (j - 1)) / 2 + (i - j);
}
// packed slot for register-resident columns j >= SC
__device__ __forceinline__ int slot_r(int i, int j) {
    return (j - SC) * N_SZ - ((j * (j - 1)) / 2 - (SC * (SC - 1)) / 2) + (i - j);
}

// triangle accessors: sm is this thread's smem lane (stride T_SZ between slots)
#define LGET(i, j) (((j) < SC) ? sm[slot_s((i), (j)) * T_SZ] : ar[slot_r((i), (j))])
#define LSET(i, j, v)                                   \
    do {                                                \
        if ((j) < SC) sm[slot_s((i), (j)) * T_SZ] = (v); \
        else          ar[slot_r((i), (j))] = (v);        \
    } while (0)

extern __shared__ float sm_tri[];  // dynamic: SM_ELEMS * T_SZ floats (71,680 B)

__global__ void __launch_bounds__(T_SZ, 3)
gll_kernel(const float* __restrict__ pred,
           const float* __restrict__ targ,
           const float* __restrict__ cov,
           float* __restrict__ out) {
    const unsigned b = blockIdx.x;   // 0..1023
    const unsigned t = threadIdx.x;  // 0..255
    float* sm = sm_tri + t;          // conflict-free: bank = t % 32 for every slot
    float ar[AR_ELEMS];

    // 32-bit indexing: max offset = 1024*16*16*256 = 67M, fits in uint32.
    const unsigned cov_base = b * (N_SZ * N_SZ * T_SZ) + t;

    // ---- load lower triangle of Sigma: cov[b,i,j,t], T innermost => coalesced.
    // Cols 0..4 go LDG->STS into private smem; cols 5..15 into registers.
#pragma unroll
    for (int i = 0; i < N_SZ; i++) {
#pragma unroll
        for (int j = 0; j <= i; j++) {
            const float v = cov[cov_base + (unsigned)((i * N_SZ + j) * T_SZ)];
            LSET(i, j, v);
        }
    }

    // ---- in-place left-looking Cholesky; diagonal slot stores 1/L_jj.
    // pivots >= 1 (Sigma = A A^T + I): product stays in [1, ~1e26], fp32-safe.
    float pivprod = 1.0f;
#pragma unroll
    for (int j = 0; j < N_SZ; j++) {
        float s = LGET(j, j);
#pragma unroll
        for (int k = 0; k < j; k++) {
            const float l = LGET(j, k);
            s -= l * l;
        }
        pivprod *= s;
        const float inv = rsqrtf(s);
        LSET(j, j, inv);
#pragma unroll
        for (int i = j + 1; i < N_SZ; i++) {
            float s2 = LGET(i, j);
#pragma unroll
            for (int k = 0; k < j; k++) {
                s2 -= LGET(i, k) * LGET(j, k);
            }
            LSET(i, j, s2 * inv);
        }
    }
    const float logdet = __logf(pivprod);

    // ---- forward solve L y = diff; quad = ||y||^2. diff loaded lazily per row
    // to keep peak register pressure low (coalesced: T innermost).
    const unsigned pt_base = b * (N_SZ * T_SZ) + t;
    float quad = 0.0f;
    float y[N_SZ];
#pragma unroll
    for (int i = 0; i < N_SZ; i++) {
        const unsigned off = pt_base + (unsigned)(i * T_SZ);
        float s = pred[off] - targ[off];
#pragma unroll
        for (int k = 0; k < i; k++) {
            s -= LGET(i, k) * y[k];
        }
        y[i] = s * LGET(i, i);  // diagonal holds 1/L_ii
        quad += y[i] * y[i];
    }

    float val = (quad + logdet) * (1.0f / ((float)B_SZ * (float)T_SZ));

    // ---- block reduction: warp shuffle, then smem across 8 warps
#pragma unroll
    for (int off = 16; off > 0; off >>= 1)
        val += __shfl_xor_sync(0xFFFFFFFFu, val, off);

    __shared__ float warp_sums[T_SZ / 32];
    const int lane = threadIdx.x & 31;
    const int wid  = threadIdx.x >> 5;
    if (lane == 0) warp_sums[wid] = val;
    __syncthreads();

    if (wid == 0) {
        float v = (lane < T_SZ / 32) ? warp_sums[lane] : 0.0f;
#pragma unroll
        for (int off = 4; off > 0; off >>= 1)
            v += __shfl_xor_sync(0xFFFFFFFFu, v, off);
        if (lane == 0) atomicAdd(out, v);
    }
}

extern "C" void kernel_launch(void* const* d_in, const int* in_sizes, int n_in,
                              void* d_out, int out_size) {
    const float* pred = (const float*)d_in[0];
    const float* targ = (const float*)d_in[1];
    const float* cov  = (const float*)d_in[2];
    float* out = (float*)d_out;

    const int smem_bytes = SM_ELEMS * T_SZ * (int)sizeof(float);  // 71,680 B
    // >48KB dynamic smem needs opt-in; attribute is sticky, ignore errors on
    // repeat calls (first, uncaptured correctness call sets it).
    cudaFuncSetAttribute(gll_kernel, cudaFuncAttributeMaxDynamicSharedMemorySize,
                         smem_bytes);

    cudaMemsetAsync(out, 0, sizeof(float));  // graph-capturable memset node
    gll_kernel<<<B_SZ, T_SZ, smem_bytes>>>(pred, targ, cov, out);
}

// round 14
// speedup vs baseline: 1.3890x; 1.3890x over previous
#include <cuda_runtime.h>

#define B_SZ 1024
#define N_SZ 16
#define T_SZ 256
// packed lower-triangular index (compile-time after unroll)
#define TRI(i, j) ((i) * ((i) + 1) / 2 + (j))

__global__ void __launch_bounds__(T_SZ, 2)
gll_kernel(const float* __restrict__ pred,
           const float* __restrict__ targ,
           const float* __restrict__ cov,
           float* __restrict__ out) {
    const unsigned b = blockIdx.x;   // 0..1023
    const unsigned t = threadIdx.x;  // 0..255

    // 32-bit indexing: max offset = 1024*16*16*256 = 67M, fits in uint32.
    const unsigned cov_base = b * (N_SZ * N_SZ * T_SZ) + t;

    // ---- load lower triangle of Sigma: cov[b,i,j,t], T innermost => coalesced
    float a[N_SZ * (N_SZ + 1) / 2];
#pragma unroll
    for (int i = 0; i < N_SZ; i++) {
#pragma unroll
        for (int j = 0; j <= i; j++) {
            a[TRI(i, j)] = cov[cov_base + (unsigned)((i * N_SZ + j) * T_SZ)];
        }
    }

    // ---- in-place left-looking Cholesky; diagonal stores 1/L_jj.
    // All reductions use TWO independent accumulators (even/odd k) to halve
    // the serial-FMA dependency chains (fp reassociation is otherwise illegal
    // for ptxas, so the source-level split is the only way to get the ILP).
    // pivots >= 1 (Sigma = A A^T + I): products stay in [1, ~1e26], fp32-safe.
    float pp0 = 1.0f, pp1 = 1.0f;
#pragma unroll
    for (int j = 0; j < N_SZ; j++) {
        float acc0 = 0.0f, acc1 = 0.0f;
#pragma unroll
        for (int k = 0; k < j; k += 2) {
            const float l = a[TRI(j, k)];
            acc0 = fmaf(l, l, acc0);
        }
#pragma unroll
        for (int k = 1; k < j; k += 2) {
            const float l = a[TRI(j, k)];
            acc1 = fmaf(l, l, acc1);
        }
        const float s = a[TRI(j, j)] - acc0 - acc1;
        if (j & 1) pp1 *= s; else pp0 *= s;
        const float inv = rsqrtf(s);
        a[TRI(j, j)] = inv;

#pragma unroll
        for (int i = j + 1; i < N_SZ; i++) {
            float u0 = 0.0f, u1 = 0.0f;
#pragma unroll
            for (int k = 0; k < j; k += 2)
                u0 = fmaf(a[TRI(i, k)], a[TRI(j, k)], u0);
#pragma unroll
            for (int k = 1; k < j; k += 2)
                u1 = fmaf(a[TRI(i, k)], a[TRI(j, k)], u1);
            const float s2 = a[TRI(i, j)] - u0 - u1;
            a[TRI(i, j)] = s2 * inv;
        }
    }
    const float logdet = __logf(pp0 * pp1);

    // ---- diff = pred - target (coalesced), after factorization
    float d[N_SZ];
    const unsigned pt_base = b * (N_SZ * T_SZ) + t;
#pragma unroll
    for (int i = 0; i < N_SZ; i++) {
        const unsigned off = pt_base + (unsigned)(i * T_SZ);
        d[i] = pred[off] - targ[off];
    }

    // ---- forward solve L y = diff; quad = ||y||^2 (diagonal holds 1/L_ii)
    float q0 = 0.0f, q1 = 0.0f;
    float y[N_SZ];
#pragma unroll
    for (int i = 0; i < N_SZ; i++) {
        float u0 = 0.0f, u1 = 0.0f;
#pragma unroll
        for (int k = 0; k < i; k += 2)
            u0 = fmaf(a[TRI(i, k)], y[k], u0);
#pragma unroll
        for (int k = 1; k < i; k += 2)
            u1 = fmaf(a[TRI(i, k)], y[k], u1);
        const float s = d[i] - u0 - u1;
        const float yi = s * a[TRI(i, i)];
        y[i] = yi;
        if (i & 1) q1 = fmaf(yi, yi, q1); else q0 = fmaf(yi, yi, q0);
    }
    const float quad = q0 + q1;

    float val = (quad + logdet) * (1.0f / ((float)B_SZ * (float)T_SZ));

    // ---- block reduction: warp shuffle, then smem across 8 warps
#pragma unroll
    for (int off = 16; off > 0; off >>= 1)
        val += __shfl_xor_sync(0xFFFFFFFFu, val, off);

    __shared__ float warp_sums[T_SZ / 32];
    const int lane = threadIdx.x & 31;
    const int wid  = threadIdx.x >> 5;
    if (lane == 0) warp_sums[wid] = val;
    __syncthreads();

    if (wid == 0) {
        float v = (lane < T_SZ / 32) ? warp_sums[lane] : 0.0f;
#pragma unroll
        for (int off = 4; off > 0; off >>= 1)
            v += __shfl_xor_sync(0xFFFFFFFFu, v, off);
        if (lane == 0) atomicAdd(out, v);
    }
}

extern "C" void kernel_launch(void* const* d_in, const int* in_sizes, int n_in,
                              void* d_out, int out_size) {
    const float* pred = (const float*)d_in[0];
    const float* targ = (const float*)d_in[1];
    const float* cov  = (const float*)d_in[2];
    float* out = (float*)d_out;

    cudaMemsetAsync(out, 0, sizeof(float));  // graph-capturable memset node
    gll_kernel<<<B_SZ, T_SZ>>>(pred, targ, cov, out);
}

// round 15
// speedup vs baseline: 2.1122x; 1.5206x over previous
#include <cuda_runtime.h>

#define B_SZ 1024
#define N_SZ 16
#define T_SZ 256
// packed lower-triangular index (compile-time after unroll)
#define TRI(i, j) ((i) * ((i) + 1) / 2 + (j))

#define RING_DEPTH 4
#define SLOT_FLOATS (N_SZ * T_SZ)   // one column buffer: 16 chunks x 256 floats = 16KB
// dynamic smem: RING_DEPTH * SLOT_FLOATS floats = 64KB per CTA

extern __shared__ float ring[];

// 4-byte per-thread async copy: no destination register => unbounded MLP.
__device__ __forceinline__ void cp4(unsigned dst_smem, const float* src) {
    asm volatile("cp.async.ca.shared.global [%0], [%1], 4;" ::
                 "r"(dst_smem), "l"(src) : "memory");
}
#define CP_COMMIT() asm volatile("cp.async.commit_group;" ::: "memory")
#define CP_WAIT(nlit) asm volatile("cp.async.wait_group " #nlit ";" ::: "memory")

// Stage column c of the lower triangle: elements (i,c), i=c..15. Thread t copies
// its own 4 bytes of each 1KB chunk; lanes coalesce to one 128B request.
__device__ __forceinline__ void issue_col(const int c, const unsigned ring_s,
                                          const float* __restrict__ cov_tb) {
    const unsigned slot = (unsigned)(c % RING_DEPTH) * SLOT_FLOATS;
#pragma unroll
    for (int i = c; i < N_SZ; i++) {
        cp4(ring_s + (slot + (unsigned)(i - c) * T_SZ) * 4u,
            cov_tb + (unsigned)((i * N_SZ + c) * T_SZ));
    }
}

__global__ void __launch_bounds__(T_SZ, 2)
gll_kernel(const float* __restrict__ pred,
           const float* __restrict__ targ,
           const float* __restrict__ cov,
           float* __restrict__ out) {
    const unsigned b = blockIdx.x;   // 0..1023
    const unsigned t = threadIdx.x;  // 0..255

    // thread's base pointers (32-bit offsets fit: 67M elements max)
    const float* cov_tb = cov + (unsigned)(b * (N_SZ * N_SZ * T_SZ)) + t;
    const unsigned ring_s =
        (unsigned)__cvta_generic_to_shared(ring) + t * 4u;

    // ---- pipeline prologue: columns 0..2 in flight
    issue_col(0, ring_s, cov_tb); CP_COMMIT();
    issue_col(1, ring_s, cov_tb); CP_COMMIT();
    issue_col(2, ring_s, cov_tb); CP_COMMIT();

    // ---- column-streaming left-looking Cholesky on the register triangle.
    // Diagonal stores 1/L_jj. pivots >= 1 (Sigma = A A^T + I): product stays
    // in [1, ~1e26], fp32-safe; one __logf at the end.
    float a[N_SZ * (N_SZ + 1) / 2];
    float pivprod = 1.0f;
#pragma unroll
    for (int j = 0; j < N_SZ; j++) {
        if (j + 3 < N_SZ) { issue_col(j + 3, ring_s, cov_tb); CP_COMMIT(); }

        // wait until column j's group has landed (<= 3 newer groups pending)
        if (j <= N_SZ - 4)      CP_WAIT(3);
        else if (j == N_SZ - 3) CP_WAIT(2);
        else if (j == N_SZ - 2) CP_WAIT(1);
        else                    CP_WAIT(0);

        // consume column j: thread-private smem -> registers (conflict-free)
        const unsigned slotf = (unsigned)(j % RING_DEPTH) * SLOT_FLOATS;
#pragma unroll
        for (int i = j; i < N_SZ; i++)
            a[TRI(i, j)] = ring[slotf + (unsigned)(i - j) * T_SZ + t];

        // compute column j (champion body, single accumulators)
        float s = a[TRI(j, j)];
#pragma unroll
        for (int k = 0; k < j; k++) {
            const float l = a[TRI(j, k)];
            s -= l * l;
        }
        pivprod *= s;
        const float inv = rsqrtf(s);
        a[TRI(j, j)] = inv;
#pragma unroll
        for (int i = j + 1; i < N_SZ; i++) {
            float s2 = a[TRI(i, j)];
#pragma unroll
            for (int k = 0; k < j; k++) {
                s2 -= a[TRI(i, k)] * a[TRI(j, k)];
            }
            a[TRI(i, j)] = s2 * inv;
        }
    }
    const float logdet = __logf(pivprod);

    // ---- diff = pred - target (coalesced), after factorization
    float d[N_SZ];
    const unsigned pt_base = b * (N_SZ * T_SZ) + t;
#pragma unroll
    for (int i = 0; i < N_SZ; i++) {
        const unsigned off = pt_base + (unsigned)(i * T_SZ);
        d[i] = pred[off] - targ[off];
    }

    // ---- forward solve L y = diff; quad = ||y||^2 (diagonal holds 1/L_ii)
    float quad = 0.0f;
    float y[N_SZ];
#pragma unroll
    for (int i = 0; i < N_SZ; i++) {
        float s = d[i];
#pragma unroll
        for (int k = 0; k < i; k++) {
            s -= a[TRI(i, k)] * y[k];
        }
        y[i] = s * a[TRI(i, i)];
        quad += y[i] * y[i];
    }

    float val = (quad + logdet) * (1.0f / ((float)B_SZ * (float)T_SZ));

    // ---- block reduction: warp shuffle, then smem across 8 warps
#pragma unroll
    for (int off = 16; off > 0; off >>= 1)
        val += __shfl_xor_sync(0xFFFFFFFFu, val, off);

    __shared__ float warp_sums[T_SZ / 32];
    const int lane = threadIdx.x & 31;
    const int wid  = threadIdx.x >> 5;
    if (lane == 0) warp_sums[wid] = val;
    __syncthreads();

    if (wid == 0) {
        float v = (lane < T_SZ / 32) ? warp_sums[lane] : 0.0f;
#pragma unroll
        for (int off = 4; off > 0; off >>= 1)
            v += __shfl_xor_sync(0xFFFFFFFFu, v, off);
        if (lane == 0) atomicAdd(out, v);
    }
}

extern "C" void kernel_launch(void* const* d_in, const int* in_sizes, int n_in,
                              void* d_out, int out_size) {
    const float* pred = (const float*)d_in[0];
    const float* targ = (const float*)d_in[1];
    const float* cov  = (const float*)d_in[2];
    float* out = (float*)d_out;

    const int smem_bytes = RING_DEPTH * SLOT_FLOATS * (int)sizeof(float);  // 65536
    // >48KB dynamic smem opt-in (sticky attribute; proven capture-safe in R12)
    cudaFuncSetAttribute(gll_kernel, cudaFuncAttributeMaxDynamicSharedMemorySize,
                         smem_bytes);

    cudaMemsetAsync(out, 0, sizeof(float));  // graph-capturable memset node
    gll_kernel<<<B_SZ, T_SZ, smem_bytes>>>(pred, targ, cov, out);
}